// round 16
// baseline (speedup 1.0000x reference)
#include <cuda_runtime.h>
#include <cuda_bf16.h>
#include <cstdint>

// ---------------- problem constants ----------------
#define NB      256     // bases
#define KD      768     // patch dim (3*16*16)
#define NIMG    64
#define NROW    27      // patch rows (= cols) per image
#define NPATIMG 729     // 27*27
#define NPTOT   (NIMG * NPATIMG)   // 46656
#define ITERS   50
#define NTASKB  448     // b_mma tasks (64 images x 7 bands)
#define GRIDB   444     // 3 * 148: 4 CTAs run two tasks

typedef unsigned long long u64;

// ---------------- device scratch (static: allocation-free) ----------------
__device__ float        g_gram[NB * NB];                 // D D^T - I (fp32)
__device__ float        g_b[(size_t)NPTOT * NB];         // feedforward drive (47.8 MB)
__device__ unsigned int g_maxbits[NIMG * NB];            // monotone-encoded running max
__device__ uint4        g_dfrag[48 * 32 * 32];           // D in B-frag order, hi/lo bf16

// ---------------- generic helpers ----------------
// softshrink(-0.01*x): the code/activation given register state r = -100*u
__device__ __forceinline__ float shneg(float x) {
    float t = fmaxf(fmaf(fabsf(x), 0.01f, -0.5f), 0.0f);
    return copysignf(t, -x);
}
__device__ __forceinline__ unsigned int enc_f(float x) {
    unsigned int b = __float_as_uint(x);
    return (b & 0x80000000u) ? ~b : (b | 0x80000000u);
}
__device__ __forceinline__ uint32_t bf2u(float a, float b) {
    __nv_bfloat162 h = __float22bfloat162_rn(make_float2(a, b));
    return *reinterpret_cast<uint32_t*>(&h);
}
__device__ __forceinline__ float bfh(float v) {
    return __bfloat162float(__float2bfloat16_rn(v));
}
__device__ __forceinline__ uint32_t smem_u32(const void* p) {
    uint32_t a;
    asm("{ .reg .u64 t; cvta.to.shared.u64 t, %1; cvt.u32.u64 %0, t; }" : "=r"(a) : "l"(p));
    return a;
}
__device__ __forceinline__ void cp_async16(uint32_t saddr, const void* gaddr) {
    asm volatile("cp.async.cg.shared.global [%0], [%1], 16;" :: "r"(saddr), "l"(gaddr));
}
#define CP_COMMIT() asm volatile("cp.async.commit_group;" ::: "memory")
#define CP_WAIT0()  asm volatile("cp.async.wait_group 0;" ::: "memory")

// m16n8k16 row.col bf16 -> f32, D accumulated in place
__device__ __forceinline__ void mma16816(float d[4], uint32_t a0, uint32_t a1,
                                         uint32_t a2, uint32_t a3,
                                         uint32_t b0, uint32_t b1) {
    asm volatile(
        "mma.sync.aligned.m16n8k16.row.col.f32.bf16.bf16.f32 "
        "{%0,%1,%2,%3}, {%4,%5,%6,%7}, {%8,%9}, {%0,%1,%2,%3};"
        : "+f"(d[0]), "+f"(d[1]), "+f"(d[2]), "+f"(d[3])
        : "r"(a0), "r"(a1), "r"(a2), "r"(a3), "r"(b0), "r"(b1));
}

// ---------------- K1: fused prep — init maxbits | gram | dfrag ----------------
// grid 288 x 256: blocks [0,64) init, [64,96) gram (8 rows each), [96,288) dfrag.
__global__ void __launch_bounds__(256) prep_kernel(const float* __restrict__ D) {
    const int blk = blockIdx.x;
    const int t   = threadIdx.x;

    if (blk < 64) {
        g_maxbits[blk * 256 + t] = 0u;
        return;
    }
    if (blk < 96) {
        // gram: rows [i0, i0+8)
        __shared__ float4 di4[8 * 192];
        const int i0 = (blk - 64) * 8;
        for (int e = t; e < 8 * 192; e += 256)
            di4[e] = ((const float4*)(D + (size_t)i0 * KD))[e];
        __syncthreads();

        float acc[8];
        #pragma unroll
        for (int i = 0; i < 8; i++) acc[i] = 0.f;
        const float4* Dt = (const float4*)(D + (size_t)t * KD);
        #pragma unroll 4
        for (int q = 0; q < 192; q++) {
            float4 v = __ldg(&Dt[q]);
            #pragma unroll
            for (int i = 0; i < 8; i++) {
                float4 g = di4[i * 192 + q];
                acc[i] += v.x * g.x + v.y * g.y + v.z * g.z + v.w * g.w;
            }
        }
        #pragma unroll
        for (int i = 0; i < 8; i++)
            g_gram[(i0 + i) * NB + t] = acc[i] - ((i0 + i == t) ? 1.0f : 0.0f);
        return;
    }
    // dfrag
    int e = (blk - 96) * 256 + t;               // 0 .. 49151
    int kk = e >> 10;
    int j  = (e >> 5) & 31;
    int ln = e & 31;
    int k0 = kk * 16 + 2 * (ln & 3);
    int n  = j * 8 + (ln >> 2);
    const float* Dr = D + (size_t)n * KD;
    float v00 = __ldg(Dr + k0),     v01 = __ldg(Dr + k0 + 1);
    float v08 = __ldg(Dr + k0 + 8), v09 = __ldg(Dr + k0 + 9);
    uint4 q;
    q.x = bf2u(v00, v01);
    q.y = bf2u(v08, v09);
    q.z = bf2u(v00 - bfh(v00), v01 - bfh(v01));
    q.w = bf2u(v08 - bfh(v08), v09 - bfh(v09));
    g_dfrag[e] = q;
}

// ---------------- K2: b = standardized patches @ D^T, double-buffered pipeline ----------------
// grid 444, task loop over 448 (4 CTAs run 2 tasks -> 3.05 waves instead of 4).
#define NCHUNK    24
#define BSM_STAT  107520                      // strip = 3*40*224 floats
#define BSM_A     108544                      // A: 2 x [128][18] uint2 = 36864 B
#define BSM_B     145408                      // B: 2 x 2048 uint4 = 65536 B
#define B2_SMEM   (BSM_B + 65536)             // 210944 B

__global__ void __launch_bounds__(512, 1) b_mma_kernel(const float* __restrict__ img) {
    extern __shared__ char sm[];
    float* strip  = (float*)sm;                    // [3][40][224]
    float* mean_s = (float*)(sm + BSM_STAT);       // [128]
    float* inv_s  = mean_s + 128;
    uint2* Apk    = (uint2*)(sm + BSM_A);          // 2 buffers of [128][18]
    uint4* Bsm    = (uint4*)(sm + BSM_B);          // 2 buffers of [2048]

    const int t    = threadIdx.x;
    const int w    = t >> 5;
    const int lane = t & 31;
    const int wm   = w & 3;
    const int wn   = w >> 2;
    const int row  = lane >> 2;
    const int l4   = lane & 3;
    const int  am  = t >> 2;
    const uint32_t bsm_addr = smem_u32(Bsm);

    #pragma unroll 1
    for (int task = blockIdx.x; task < NTASKB; task += GRIDB) {

    __syncthreads();   // prior task's staging reads of strip/stats fully done

    const int im   = task / 7;
    const int band = task - im * 7;
    const int py0  = band * 4;
    const int nr   = (band == 6) ? 3 : 4;
    const int npat = 27 * nr;
    const int srows = 8 * nr + 8;

    // ---- load strip ----
    const float* ib = img + (size_t)im * 3 * 224 * 224 + (size_t)(py0 * 8) * 224;
    const int tot = 3 * srows * 224;
    for (int e = t; e < tot; e += 512) {
        int c   = e / (srows * 224);
        int rem = e - c * (srows * 224);
        strip[(c * 40) * 224 + rem] = ib[(size_t)c * 224 * 224 + rem];
    }
    __syncthreads();

    // ---- per-patch stats: 4 lanes per patch ----
    {
        int p0 = t >> 2;
        int p  = (p0 < npat) ? p0 : (npat - 1);
        int pl4 = t & 3;
        int pr = p / 27, pc = p - pr * 27;
        int y0 = pr * 8, x0 = pc * 8;
        float sm_ = 0.f, sq = 0.f;
        for (int d = pl4; d < KD; d += 4) {
            int c   = d >> 8;
            int r16 = (d >> 4) & 15;
            int pw  = d & 15;
            float v = strip[(c * 40 + y0 + r16) * 224 + x0 + pw];
            sm_ += v; sq += v * v;
        }
        sm_ += __shfl_down_sync(0xffffffffu, sm_, 2);
        sq  += __shfl_down_sync(0xffffffffu, sq,  2);
        sm_ += __shfl_down_sync(0xffffffffu, sm_, 1);
        sq  += __shfl_down_sync(0xffffffffu, sq,  1);
        if (pl4 == 0 && p0 < npat) {
            float m   = sm_ * (1.0f / 768.0f);
            float var = fmaxf(sq - sm_ * sm_ * (1.0f / 768.0f), 0.0f) * (1.0f / 767.0f);
            mean_s[p0] = m;
            inv_s[p0]  = 1.0f / (sqrtf(var) + 1e-8f);
        }
    }

    float acc[2][8][4];
    #pragma unroll
    for (int mt = 0; mt < 2; mt++)
        #pragma unroll
        for (int j = 0; j < 8; j++)
            #pragma unroll
            for (int c = 0; c < 4; c++) acc[mt][j][c] = 0.f;

    const bool amv = am < npat;
    const int  apr = amv ? am / 27 : 0;
    const int  apc = amv ? (am - apr * 27) : 0;

    __syncthreads();   // stats visible

    const float amm = amv ? mean_s[am] : 0.f;
    const float aiv = amv ? inv_s[am]  : 0.f;

    #define STAGE_A(ch, buf) do {                                                   \
        uint2* ap = Apk + (buf) * (128 * 18);                                       \
        _Pragma("unroll")                                                           \
        for (int i = 0; i < 4; i++) {                                               \
            int p2 = (t & 3) * 4 + i;                                               \
            int d  = (ch) * 32 + 2 * p2;                                            \
            int c   = d >> 8;                                                       \
            int r16 = (d >> 4) & 15;                                                \
            int pw  = d & 15;                                                       \
            float v0 = 0.f, v1 = 0.f;                                               \
            if (amv) {                                                              \
                const float* sp = &strip[(c * 40 + apr * 8 + r16) * 224 + apc * 8 + pw]; \
                v0 = (sp[0] - amm) * aiv;                                           \
                v1 = (sp[1] - amm) * aiv;                                           \
            }                                                                       \
            uint2 pk;                                                               \
            pk.x = bf2u(v0, v1);                                                    \
            pk.y = bf2u(v0 - bfh(v0), v1 - bfh(v1));                                \
            ap[am * 18 + p2] = pk;                                                  \
        }                                                                           \
    } while (0)

    #define STAGE_B(ch, buf) do {                                                   \
        const uint4* gsrc = g_dfrag + (size_t)(ch) * 2048;                          \
        uint32_t sdst = bsm_addr + (buf) * 32768;                                   \
        _Pragma("unroll")                                                           \
        for (int k = 0; k < 4; k++)                                                 \
            cp_async16(sdst + (k * 512 + t) * 16, gsrc + k * 512 + t);              \
        CP_COMMIT();                                                                \
    } while (0)

    STAGE_A(0, 0);
    STAGE_B(0, 0);

    #pragma unroll 1
    for (int ch = 0; ch < NCHUNK; ch++) {
        const int cur = ch & 1;
        CP_WAIT0();
        __syncthreads();   // B(ch), A(ch) ready; alt buffer free

        if (ch + 1 < NCHUNK) STAGE_B(ch + 1, cur ^ 1);

        const uint2* ap = Apk + cur * (128 * 18);
        const uint4* bp = Bsm + cur * 2048;

        #pragma unroll
        for (int kkl = 0; kkl < 2; kkl++) {
            uint2 aa[2][4];
            #pragma unroll
            for (int mt = 0; mt < 2; mt++) {
                int mrow = wm * 32 + mt * 16 + row;
                aa[mt][0] = ap[mrow * 18 + kkl * 8 + l4];
                aa[mt][1] = ap[(mrow + 8) * 18 + kkl * 8 + l4];
                aa[mt][2] = ap[mrow * 18 + kkl * 8 + 4 + l4];
                aa[mt][3] = ap[(mrow + 8) * 18 + kkl * 8 + 4 + l4];
            }
            #pragma unroll
            for (int j = 0; j < 8; j++) {
                uint4 q = bp[(kkl * 32 + wn * 8 + j) * 32 + lane];
                #pragma unroll
                for (int mt = 0; mt < 2; mt++) {
                    mma16816(acc[mt][j], aa[mt][0].x, aa[mt][1].x, aa[mt][2].x, aa[mt][3].x, q.x, q.y);
                    mma16816(acc[mt][j], aa[mt][0].x, aa[mt][1].x, aa[mt][2].x, aa[mt][3].x, q.z, q.w);
                    mma16816(acc[mt][j], aa[mt][0].y, aa[mt][1].y, aa[mt][2].y, aa[mt][3].y, q.x, q.y);
                }
            }
        }

        if (ch + 1 < NCHUNK) STAGE_A(ch + 1, cur ^ 1);
    }

    // ---- epilogue: write b ----
    const int pbase = (im * NROW + py0) * NROW;
    const int kp = 2 * l4;
    #pragma unroll
    for (int mt = 0; mt < 2; mt++) {
        int m0 = wm * 32 + mt * 16 + row;
        int m1 = m0 + 8;
        #pragma unroll
        for (int j = 0; j < 8; j++) {
            int n0 = wn * 64 + j * 8 + kp;
            if (m0 < npat) {
                int gp = pbase + (m0 / 27) * NROW + (m0 % 27);
                *(float2*)(g_b + (size_t)gp * NB + n0) = make_float2(acc[mt][j][0], acc[mt][j][1]);
            }
            if (m1 < npat) {
                int gp = pbase + (m1 / 27) * NROW + (m1 % 27);
                *(float2*)(g_b + (size_t)gp * NB + n0) = make_float2(acc[mt][j][2], acc[mt][j][3]);
            }
        }
    }

    }   // task loop
}

// ---------------- K3: LCA via mma.sync (bf16), in-register chaining ----------------
// EXACT round-9 structure (best measured): one warp = 16 patches x 256 bases,
// no syncs in mainloop, B-frags for (j, j+16) paired in one uint4 (LDS.128).
#define LCA_SMEM (131072 + 2048)
#define NPB ((NPTOT + 127) / 128)   // 365

__global__ void __launch_bounds__(256, 1) lca_mma_kernel() {
    extern __shared__ char smraw[];
    uint4*        bsm4  = (uint4*)smraw;                   // [8192] paired gram frags
    unsigned int* stage = (unsigned int*)(smraw + 131072); // [2][256] per-CTA max

    const int tid  = threadIdx.x;
    const int w    = tid >> 5;
    const int lane = tid & 31;

    if (tid < 256) { stage[tid] = 0u; stage[tid + 256] = 0u; }

    // pre-fragment gram (bf16) paired: entry (kk*16 + j)*32 + ln holds frags for
    // n-tiles j and j+16:  k0 = kk*16 + 2(ln&3), n1 = j*8 + (ln>>2), n2 = n1 + 128
    for (int e = tid; e < 8192; e += 256) {
        int kk = e >> 9;
        int j  = (e >> 5) & 15;
        int ln = e & 31;
        int k0 = kk * 16 + 2 * (ln & 3);
        int n1 = j * 8 + (ln >> 2);
        int n2 = n1 + 128;
        uint4 q;
        q.x = bf2u(g_gram[k0 * NB + n1],       g_gram[(k0 + 1) * NB + n1]);
        q.y = bf2u(g_gram[(k0 + 8) * NB + n1], g_gram[(k0 + 9) * NB + n1]);
        q.z = bf2u(g_gram[k0 * NB + n2],       g_gram[(k0 + 1) * NB + n2]);
        q.w = bf2u(g_gram[(k0 + 8) * NB + n2], g_gram[(k0 + 9) * NB + n2]);
        bsm4[e] = q;
    }
    __syncthreads();

    // ---- per-warp patch assignment ----
    const int base    = blockIdx.x * 128 + w * 16;
    const int row_lo  = lane >> 2;
    const int gpl     = base + row_lo;
    const int gph     = gpl + 8;
    const bool vl     = gpl < NPTOT;
    const bool vh     = gph < NPTOT;
    const float fl    = vl ? 1.0f : 0.0f;
    const float fh    = vh ? 1.0f : 0.0f;
    const float2* blf = (const float2*)(g_b + (size_t)(vl ? gpl : 0) * NB + 2 * (lane & 3));
    const float2* bhf = (const float2*)(g_b + (size_t)(vh ? gph : 0) * NB + 2 * (lane & 3));

    // ---- warm start: max |b| over the warp's 16x256 block ----
    float mx = 0.f;
    #pragma unroll
    for (int j = 0; j < 32; j++) {
        float2 x = __ldg(blf + 4 * j);
        float2 y = __ldg(bhf + 4 * j);
        mx = fmaxf(mx, fmaxf(fl * fmaxf(fabsf(x.x), fabsf(x.y)),
                             fh * fmaxf(fabsf(y.x), fabsf(y.y))));
    }
    float m1 = __uint_as_float(__reduce_max_sync(0xffffffffu, __float_as_uint(mx)));

    int S = 0; float gg = 1.0f;
    while (S < ITERS - 1 && (1.0f - gg) * m1 < 0.4999f) { S++; gg *= 0.99f; }
    const int   R = ITERS - S;
    const float f = -(1.0f - gg) * 100.0f;   // r = -100 * u

    float r[32][4];
    #pragma unroll
    for (int j = 0; j < 32; j++) {
        float2 x = __ldg(blf + 4 * j);
        float2 y = __ldg(bhf + 4 * j);
        r[j][0] = f * (x.x * fl);
        r[j][1] = f * (x.y * fl);
        r[j][2] = f * (y.x * fh);
        r[j][3] = f * (y.y * fh);
    }

    const uint4* bwl = bsm4 + lane;

    #pragma unroll 1
    for (int it = 0; it < R; it++) {
        uint32_t a[16][4];
        #pragma unroll
        for (int kk = 0; kk < 16; kk++) {
            a[kk][0] = bf2u(shneg(r[2*kk][0]),   shneg(r[2*kk][1]));
            a[kk][1] = bf2u(shneg(r[2*kk][2]),   shneg(r[2*kk][3]));
            a[kk][2] = bf2u(shneg(r[2*kk+1][0]), shneg(r[2*kk+1][1]));
            a[kk][3] = bf2u(shneg(r[2*kk+1][2]), shneg(r[2*kk+1][3]));
        }
        #pragma unroll
        for (int j = 0; j < 32; j++) {
            float2 x = __ldg(blf + 4 * j);
            float2 y = __ldg(bhf + 4 * j);
            r[j][0] = fmaf(r[j][0], 0.99f, -(x.x * fl));
            r[j][1] = fmaf(r[j][1], 0.99f, -(x.y * fl));
            r[j][2] = fmaf(r[j][2], 0.99f, -(y.x * fh));
            r[j][3] = fmaf(r[j][3], 0.99f, -(y.y * fh));
        }
        #pragma unroll
        for (int kk = 0; kk < 16; kk++) {
            #pragma unroll
            for (int j = 0; j < 16; j++) {
                uint4 q = bwl[(kk * 16 + j) * 32];
                mma16816(r[j],      a[kk][0], a[kk][1], a[kk][2], a[kk][3], q.x, q.y);
                mma16816(r[j + 16], a[kk][0], a[kk][1], a[kk][2], a[kk][3], q.z, q.w);
            }
        }
    }

    // ---- epilogue: per-CTA smem max stage, then global ----
    const int im_base = (blockIdx.x * 128) / NPATIMG;
    const int iml = vl ? (gpl / NPATIMG - im_base) : 0;
    const int imh = vh ? (gph / NPATIMG - im_base) : 0;
    #pragma unroll
    for (int j = 0; j < 32; j++) {
        int n0 = 2 * (lane & 3) + 8 * j;
        if (vl) {
            atomicMax(&stage[iml * NB + n0],     enc_f(shneg(r[j][0])));
            atomicMax(&stage[iml * NB + n0 + 1], enc_f(shneg(r[j][1])));
        }
        if (vh) {
            atomicMax(&stage[imh * NB + n0],     enc_f(shneg(r[j][2])));
            atomicMax(&stage[imh * NB + n0 + 1], enc_f(shneg(r[j][3])));
        }
    }
    __syncthreads();

    const int last_p  = min(blockIdx.x * 128 + 127, NPTOT - 1);
    const int im_last = last_p / NPATIMG;
    #pragma unroll
    for (int c = tid; c < 512; c += 256) {
        int li = c >> 8, n = c & 255;
        int img = im_base + li;
        if (img <= im_last && stage[c])
            atomicMax(&g_maxbits[img * NB + n], stage[c]);
    }
}

// ---------------- K4: decode running max to output ----------------
__global__ void finalize_kernel(float* __restrict__ out) {
    int idx = blockIdx.x * NB + threadIdx.x;
    unsigned int k = g_maxbits[idx];
    out[idx] = (k & 0x80000000u) ? __uint_as_float(k & 0x7fffffffu)
                                 : __uint_as_float(~k);
}

// ---------------- launch ----------------
extern "C" void kernel_launch(void* const* d_in, const int* in_sizes, int n_in,
                              void* d_out, int out_size) {
    const float* image = (const float*)d_in[0];
    const float* dict  = (const float*)d_in[1];
    float* out = (float*)d_out;

    cudaFuncSetAttribute(b_mma_kernel,   cudaFuncAttributeMaxDynamicSharedMemorySize, B2_SMEM);
    cudaFuncSetAttribute(lca_mma_kernel, cudaFuncAttributeMaxDynamicSharedMemorySize, LCA_SMEM);

    prep_kernel<<<288, 256>>>(dict);
    b_mma_kernel<<<GRIDB, 512, B2_SMEM>>>(image);
    lca_mma_kernel<<<NPB, 256, LCA_SMEM>>>();
    finalize_kernel<<<NIMG, NB>>>(out);
}

// round 17
// speedup vs baseline: 1.0593x; 1.0593x over previous
#include <cuda_runtime.h>
#include <cuda_bf16.h>
#include <cstdint>

// ---------------- problem constants ----------------
#define NB      256     // bases
#define KD      768     // patch dim (3*16*16)
#define NIMG    64
#define NROW    27      // patch rows (= cols) per image
#define NPATIMG 729     // 27*27
#define NPTOT   (NIMG * NPATIMG)   // 46656
#define ITERS   50

typedef unsigned long long u64;

// ---------------- device scratch (static: allocation-free) ----------------
__device__ float        g_gram[NB * NB];                 // D D^T - I (fp32)
__device__ float        g_b[(size_t)NPTOT * NB];         // feedforward drive (47.8 MB)
__device__ unsigned int g_maxbits[NIMG * NB];            // monotone-encoded running max
__device__ uint4        g_dfrag[48 * 32 * 32];           // D in B-frag order, hi/lo bf16

// ---------------- generic helpers ----------------
// softshrink(-0.01*x): the code/activation given register state r = -100*u
__device__ __forceinline__ float shneg(float x) {
    float t = fmaxf(fmaf(fabsf(x), 0.01f, -0.5f), 0.0f);
    return copysignf(t, -x);
}
__device__ __forceinline__ unsigned int enc_f(float x) {
    unsigned int b = __float_as_uint(x);
    return (b & 0x80000000u) ? ~b : (b | 0x80000000u);
}
__device__ __forceinline__ uint32_t bf2u(float a, float b) {
    __nv_bfloat162 h = __float22bfloat162_rn(make_float2(a, b));
    return *reinterpret_cast<uint32_t*>(&h);
}
__device__ __forceinline__ float bfh(float v) {
    return __bfloat162float(__float2bfloat16_rn(v));
}
__device__ __forceinline__ uint32_t smem_u32(const void* p) {
    uint32_t a;
    asm("{ .reg .u64 t; cvta.to.shared.u64 t, %1; cvt.u32.u64 %0, t; }" : "=r"(a) : "l"(p));
    return a;
}
__device__ __forceinline__ void cp_async16(uint32_t saddr, const void* gaddr) {
    asm volatile("cp.async.cg.shared.global [%0], [%1], 16;" :: "r"(saddr), "l"(gaddr));
}
#define CP_COMMIT() asm volatile("cp.async.commit_group;" ::: "memory")
#define CP_WAIT0()  asm volatile("cp.async.wait_group 0;" ::: "memory")

// m16n8k16 row.col bf16 -> f32, D accumulated in place
__device__ __forceinline__ void mma16816(float d[4], uint32_t a0, uint32_t a1,
                                         uint32_t a2, uint32_t a3,
                                         uint32_t b0, uint32_t b1) {
    asm volatile(
        "mma.sync.aligned.m16n8k16.row.col.f32.bf16.bf16.f32 "
        "{%0,%1,%2,%3}, {%4,%5,%6,%7}, {%8,%9}, {%0,%1,%2,%3};"
        : "+f"(d[0]), "+f"(d[1]), "+f"(d[2]), "+f"(d[3])
        : "r"(a0), "r"(a1), "r"(a2), "r"(a3), "r"(b0), "r"(b1));
}

// ---------------- K1: fused prep — init maxbits | gram | dfrag ----------------
// grid 288 x 256: blocks [0,64) init, [64,96) gram (8 rows each), [96,288) dfrag.
__global__ void __launch_bounds__(256) prep_kernel(const float* __restrict__ D) {
    const int blk = blockIdx.x;
    const int t   = threadIdx.x;

    if (blk < 64) {
        g_maxbits[blk * 256 + t] = 0u;
        return;
    }
    if (blk < 96) {
        // gram: rows [i0, i0+8)
        __shared__ float4 di4[8 * 192];
        const int i0 = (blk - 64) * 8;
        for (int e = t; e < 8 * 192; e += 256)
            di4[e] = ((const float4*)(D + (size_t)i0 * KD))[e];
        __syncthreads();

        float acc[8];
        #pragma unroll
        for (int i = 0; i < 8; i++) acc[i] = 0.f;
        const float4* Dt = (const float4*)(D + (size_t)t * KD);
        #pragma unroll 4
        for (int q = 0; q < 192; q++) {
            float4 v = __ldg(&Dt[q]);
            #pragma unroll
            for (int i = 0; i < 8; i++) {
                float4 g = di4[i * 192 + q];
                acc[i] += v.x * g.x + v.y * g.y + v.z * g.z + v.w * g.w;
            }
        }
        #pragma unroll
        for (int i = 0; i < 8; i++)
            g_gram[(i0 + i) * NB + t] = acc[i] - ((i0 + i == t) ? 1.0f : 0.0f);
        return;
    }
    // dfrag
    int e = (blk - 96) * 256 + t;               // 0 .. 49151
    int kk = e >> 10;
    int j  = (e >> 5) & 31;
    int ln = e & 31;
    int k0 = kk * 16 + 2 * (ln & 3);
    int n  = j * 8 + (ln >> 2);
    const float* Dr = D + (size_t)n * KD;
    float v00 = __ldg(Dr + k0),     v01 = __ldg(Dr + k0 + 1);
    float v08 = __ldg(Dr + k0 + 8), v09 = __ldg(Dr + k0 + 9);
    uint4 q;
    q.x = bf2u(v00, v01);
    q.y = bf2u(v08, v09);
    q.z = bf2u(v00 - bfh(v00), v01 - bfh(v01));
    q.w = bf2u(v08 - bfh(v08), v09 - bfh(v09));
    g_dfrag[e] = q;
}

// ---------------- K2: b = standardized patches @ D^T, double-buffered pipeline ----------------
// Round-15 body verbatim (best measured): grid 448, one task per CTA.
// Issue order per chunk: cp.async B(ch+1) first, then MMAs, then STAGE_A(ch+1).
#define NCHUNK    24
#define BSM_STAT  107520                      // strip = 3*40*224 floats
#define BSM_A     108544                      // A: 2 x [128][18] uint2 = 36864 B
#define BSM_B     145408                      // B: 2 x 2048 uint4 = 65536 B
#define B2_SMEM   (BSM_B + 65536)             // 210944 B

__global__ void __launch_bounds__(512, 1) b_mma_kernel(const float* __restrict__ img) {
    extern __shared__ char sm[];
    float* strip  = (float*)sm;                    // [3][40][224]
    float* mean_s = (float*)(sm + BSM_STAT);       // [128]
    float* inv_s  = mean_s + 128;
    uint2* Apk    = (uint2*)(sm + BSM_A);          // 2 buffers of [128][18]
    uint4* Bsm    = (uint4*)(sm + BSM_B);          // 2 buffers of [2048]

    const int blk  = blockIdx.x;
    const int im   = blk / 7;
    const int band = blk - im * 7;
    const int py0  = band * 4;
    const int nr   = (band == 6) ? 3 : 4;
    const int npat = 27 * nr;
    const int srows = 8 * nr + 8;
    const int t = threadIdx.x;

    // ---- load strip ----
    const float* ib = img + (size_t)im * 3 * 224 * 224 + (size_t)(py0 * 8) * 224;
    const int tot = 3 * srows * 224;
    for (int e = t; e < tot; e += 512) {
        int c   = e / (srows * 224);
        int rem = e - c * (srows * 224);
        strip[(c * 40) * 224 + rem] = ib[(size_t)c * 224 * 224 + rem];
    }
    __syncthreads();

    // ---- per-patch stats: 4 lanes per patch ----
    {
        int p0 = t >> 2;
        int p  = (p0 < npat) ? p0 : (npat - 1);
        int l4 = t & 3;
        int pr = p / 27, pc = p - pr * 27;
        int y0 = pr * 8, x0 = pc * 8;
        float sm_ = 0.f, sq = 0.f;
        for (int d = l4; d < KD; d += 4) {
            int c   = d >> 8;
            int r16 = (d >> 4) & 15;
            int pw  = d & 15;
            float v = strip[(c * 40 + y0 + r16) * 224 + x0 + pw];
            sm_ += v; sq += v * v;
        }
        sm_ += __shfl_down_sync(0xffffffffu, sm_, 2);
        sq  += __shfl_down_sync(0xffffffffu, sq,  2);
        sm_ += __shfl_down_sync(0xffffffffu, sm_, 1);
        sq  += __shfl_down_sync(0xffffffffu, sq,  1);
        if (l4 == 0 && p0 < npat) {
            float m   = sm_ * (1.0f / 768.0f);
            float var = fmaxf(sq - sm_ * sm_ * (1.0f / 768.0f), 0.0f) * (1.0f / 767.0f);
            mean_s[p0] = m;
            inv_s[p0]  = 1.0f / (sqrtf(var) + 1e-8f);
        }
    }

    const int w    = t >> 5;
    const int lane = t & 31;
    const int wm   = w & 3;
    const int wn   = w >> 2;
    const int row  = lane >> 2;
    const int l4   = lane & 3;

    float acc[2][8][4];
    #pragma unroll
    for (int mt = 0; mt < 2; mt++)
        #pragma unroll
        for (int j = 0; j < 8; j++)
            #pragma unroll
            for (int c = 0; c < 4; c++) acc[mt][j][c] = 0.f;

    const int  am  = t >> 2;
    const bool amv = am < npat;
    const int  apr = amv ? am / 27 : 0;
    const int  apc = amv ? (am - apr * 27) : 0;

    __syncthreads();   // stats visible

    const float amm = amv ? mean_s[am] : 0.f;
    const float aiv = amv ? inv_s[am]  : 0.f;

    const uint32_t bsm_addr = smem_u32(Bsm);

    #define STAGE_A(ch, buf) do {                                                   \
        uint2* ap = Apk + (buf) * (128 * 18);                                       \
        _Pragma("unroll")                                                           \
        for (int i = 0; i < 4; i++) {                                               \
            int p2 = (t & 3) * 4 + i;                                               \
            int d  = (ch) * 32 + 2 * p2;                                            \
            int c   = d >> 8;                                                       \
            int r16 = (d >> 4) & 15;                                                \
            int pw  = d & 15;                                                       \
            float v0 = 0.f, v1 = 0.f;                                               \
            if (amv) {                                                              \
                const float* sp = &strip[(c * 40 + apr * 8 + r16) * 224 + apc * 8 + pw]; \
                v0 = (sp[0] - amm) * aiv;                                           \
                v1 = (sp[1] - amm) * aiv;                                           \
            }                                                                       \
            uint2 pk;                                                               \
            pk.x = bf2u(v0, v1);                                                    \
            pk.y = bf2u(v0 - bfh(v0), v1 - bfh(v1));                                \
            ap[am * 18 + p2] = pk;                                                  \
        }                                                                           \
    } while (0)

    #define STAGE_B(ch, buf) do {                                                   \
        const uint4* gsrc = g_dfrag + (size_t)(ch) * 2048;                          \
        uint32_t sdst = bsm_addr + (buf) * 32768;                                   \
        _Pragma("unroll")                                                           \
        for (int k = 0; k < 4; k++)                                                 \
            cp_async16(sdst + (k * 512 + t) * 16, gsrc + k * 512 + t);              \
        CP_COMMIT();                                                                \
    } while (0)

    STAGE_A(0, 0);
    STAGE_B(0, 0);

    #pragma unroll 1
    for (int ch = 0; ch < NCHUNK; ch++) {
        const int cur = ch & 1;
        CP_WAIT0();
        __syncthreads();   // B(ch), A(ch) ready; alt buffer free

        // (1) cheap async B prefetch for ch+1 — latency hides under the MMAs
        if (ch + 1 < NCHUNK) STAGE_B(ch + 1, cur ^ 1);

        // (2) MMAs on chunk ch — tensor pipe busy immediately after the sync
        const uint2* ap = Apk + cur * (128 * 18);
        const uint4* bp = Bsm + cur * 2048;

        #pragma unroll
        for (int kkl = 0; kkl < 2; kkl++) {
            uint2 aa[2][4];
            #pragma unroll
            for (int mt = 0; mt < 2; mt++) {
                int mrow = wm * 32 + mt * 16 + row;
                aa[mt][0] = ap[mrow * 18 + kkl * 8 + l4];
                aa[mt][1] = ap[(mrow + 8) * 18 + kkl * 8 + l4];
                aa[mt][2] = ap[mrow * 18 + kkl * 8 + 4 + l4];
                aa[mt][3] = ap[(mrow + 8) * 18 + kkl * 8 + 4 + l4];
            }
            #pragma unroll
            for (int j = 0; j < 8; j++) {
                uint4 q = bp[(kkl * 32 + wn * 8 + j) * 32 + lane];
                #pragma unroll
                for (int mt = 0; mt < 2; mt++) {
                    mma16816(acc[mt][j], aa[mt][0].x, aa[mt][1].x, aa[mt][2].x, aa[mt][3].x, q.x, q.y);
                    mma16816(acc[mt][j], aa[mt][0].x, aa[mt][1].x, aa[mt][2].x, aa[mt][3].x, q.z, q.w);
                    mma16816(acc[mt][j], aa[mt][0].y, aa[mt][1].y, aa[mt][2].y, aa[mt][3].y, q.x, q.y);
                }
            }
        }

        // (3) expensive A staging for ch+1 — executes while the tensor pipe drains
        if (ch + 1 < NCHUNK) STAGE_A(ch + 1, cur ^ 1);
    }

    // ---- epilogue: write b ----
    const int pbase = (im * NROW + py0) * NROW;
    const int kp = 2 * l4;
    #pragma unroll
    for (int mt = 0; mt < 2; mt++) {
        int m0 = wm * 32 + mt * 16 + row;
        int m1 = m0 + 8;
        #pragma unroll
        for (int j = 0; j < 8; j++) {
            int n0 = wn * 64 + j * 8 + kp;
            if (m0 < npat) {
                int gp = pbase + (m0 / 27) * NROW + (m0 % 27);
                *(float2*)(g_b + (size_t)gp * NB + n0) = make_float2(acc[mt][j][0], acc[mt][j][1]);
            }
            if (m1 < npat) {
                int gp = pbase + (m1 / 27) * NROW + (m1 % 27);
                *(float2*)(g_b + (size_t)gp * NB + n0) = make_float2(acc[mt][j][2], acc[mt][j][3]);
            }
        }
    }
}

// ---------------- K3: LCA via mma.sync (bf16), in-register chaining ----------------
// EXACT round-9 structure (best measured): one warp = 16 patches x 256 bases,
// no syncs in mainloop, B-frags for (j, j+16) paired in one uint4 (LDS.128).
#define LCA_SMEM (131072 + 2048)
#define NPB ((NPTOT + 127) / 128)   // 365

__global__ void __launch_bounds__(256, 1) lca_mma_kernel() {
    extern __shared__ char smraw[];
    uint4*        bsm4  = (uint4*)smraw;                   // [8192] paired gram frags
    unsigned int* stage = (unsigned int*)(smraw + 131072); // [2][256] per-CTA max

    const int tid  = threadIdx.x;
    const int w    = tid >> 5;
    const int lane = tid & 31;

    if (tid < 256) { stage[tid] = 0u; stage[tid + 256] = 0u; }

    // pre-fragment gram (bf16) paired: entry (kk*16 + j)*32 + ln holds frags for
    // n-tiles j and j+16:  k0 = kk*16 + 2(ln&3), n1 = j*8 + (ln>>2), n2 = n1 + 128
    for (int e = tid; e < 8192; e += 256) {
        int kk = e >> 9;
        int j  = (e >> 5) & 15;
        int ln = e & 31;
        int k0 = kk * 16 + 2 * (ln & 3);
        int n1 = j * 8 + (ln >> 2);
        int n2 = n1 + 128;
        uint4 q;
        q.x = bf2u(g_gram[k0 * NB + n1],       g_gram[(k0 + 1) * NB + n1]);
        q.y = bf2u(g_gram[(k0 + 8) * NB + n1], g_gram[(k0 + 9) * NB + n1]);
        q.z = bf2u(g_gram[k0 * NB + n2],       g_gram[(k0 + 1) * NB + n2]);
        q.w = bf2u(g_gram[(k0 + 8) * NB + n2], g_gram[(k0 + 9) * NB + n2]);
        bsm4[e] = q;
    }
    __syncthreads();

    // ---- per-warp patch assignment ----
    const int base    = blockIdx.x * 128 + w * 16;
    const int row_lo  = lane >> 2;
    const int gpl     = base + row_lo;
    const int gph     = gpl + 8;
    const bool vl     = gpl < NPTOT;
    const bool vh     = gph < NPTOT;
    const float fl    = vl ? 1.0f : 0.0f;
    const float fh    = vh ? 1.0f : 0.0f;
    const float2* blf = (const float2*)(g_b + (size_t)(vl ? gpl : 0) * NB + 2 * (lane & 3));
    const float2* bhf = (const float2*)(g_b + (size_t)(vh ? gph : 0) * NB + 2 * (lane & 3));

    // ---- warm start: max |b| over the warp's 16x256 block ----
    float mx = 0.f;
    #pragma unroll
    for (int j = 0; j < 32; j++) {
        float2 x = __ldg(blf + 4 * j);
        float2 y = __ldg(bhf + 4 * j);
        mx = fmaxf(mx, fmaxf(fl * fmaxf(fabsf(x.x), fabsf(x.y)),
                             fh * fmaxf(fabsf(y.x), fabsf(y.y))));
    }
    float m1 = __uint_as_float(__reduce_max_sync(0xffffffffu, __float_as_uint(mx)));

    int S = 0; float gg = 1.0f;
    while (S < ITERS - 1 && (1.0f - gg) * m1 < 0.4999f) { S++; gg *= 0.99f; }
    const int   R = ITERS - S;
    const float f = -(1.0f - gg) * 100.0f;   // r = -100 * u

    float r[32][4];
    #pragma unroll
    for (int j = 0; j < 32; j++) {
        float2 x = __ldg(blf + 4 * j);
        float2 y = __ldg(bhf + 4 * j);
        r[j][0] = f * (x.x * fl);
        r[j][1] = f * (x.y * fl);
        r[j][2] = f * (y.x * fh);
        r[j][3] = f * (y.y * fh);
    }

    const uint4* bwl = bsm4 + lane;

    #pragma unroll 1
    for (int it = 0; it < R; it++) {
        uint32_t a[16][4];
        #pragma unroll
        for (int kk = 0; kk < 16; kk++) {
            a[kk][0] = bf2u(shneg(r[2*kk][0]),   shneg(r[2*kk][1]));
            a[kk][1] = bf2u(shneg(r[2*kk][2]),   shneg(r[2*kk][3]));
            a[kk][2] = bf2u(shneg(r[2*kk+1][0]), shneg(r[2*kk+1][1]));
            a[kk][3] = bf2u(shneg(r[2*kk+1][2]), shneg(r[2*kk+1][3]));
        }
        #pragma unroll
        for (int j = 0; j < 32; j++) {
            float2 x = __ldg(blf + 4 * j);
            float2 y = __ldg(bhf + 4 * j);
            r[j][0] = fmaf(r[j][0], 0.99f, -(x.x * fl));
            r[j][1] = fmaf(r[j][1], 0.99f, -(x.y * fl));
            r[j][2] = fmaf(r[j][2], 0.99f, -(y.x * fh));
            r[j][3] = fmaf(r[j][3], 0.99f, -(y.y * fh));
        }
        #pragma unroll
        for (int kk = 0; kk < 16; kk++) {
            #pragma unroll
            for (int j = 0; j < 16; j++) {
                uint4 q = bwl[(kk * 16 + j) * 32];
                mma16816(r[j],      a[kk][0], a[kk][1], a[kk][2], a[kk][3], q.x, q.y);
                mma16816(r[j + 16], a[kk][0], a[kk][1], a[kk][2], a[kk][3], q.z, q.w);
            }
        }
    }

    // ---- epilogue: per-CTA smem max stage, then global ----
    const int im_base = (blockIdx.x * 128) / NPATIMG;
    const int iml = vl ? (gpl / NPATIMG - im_base) : 0;
    const int imh = vh ? (gph / NPATIMG - im_base) : 0;
    #pragma unroll
    for (int j = 0; j < 32; j++) {
        int n0 = 2 * (lane & 3) + 8 * j;
        if (vl) {
            atomicMax(&stage[iml * NB + n0],     enc_f(shneg(r[j][0])));
            atomicMax(&stage[iml * NB + n0 + 1], enc_f(shneg(r[j][1])));
        }
        if (vh) {
            atomicMax(&stage[imh * NB + n0],     enc_f(shneg(r[j][2])));
            atomicMax(&stage[imh * NB + n0 + 1], enc_f(shneg(r[j][3])));
        }
    }
    __syncthreads();

    const int last_p  = min(blockIdx.x * 128 + 127, NPTOT - 1);
    const int im_last = last_p / NPATIMG;
    #pragma unroll
    for (int c = tid; c < 512; c += 256) {
        int li = c >> 8, n = c & 255;
        int img = im_base + li;
        if (img <= im_last && stage[c])
            atomicMax(&g_maxbits[img * NB + n], stage[c]);
    }
}

// ---------------- K4: decode running max to output ----------------
__global__ void finalize_kernel(float* __restrict__ out) {
    int idx = blockIdx.x * NB + threadIdx.x;
    unsigned int k = g_maxbits[idx];
    out[idx] = (k & 0x80000000u) ? __uint_as_float(k & 0x7fffffffu)
                                 : __uint_as_float(~k);
}

// ---------------- launch ----------------
extern "C" void kernel_launch(void* const* d_in, const int* in_sizes, int n_in,
                              void* d_out, int out_size) {
    const float* image = (const float*)d_in[0];
    const float* dict  = (const float*)d_in[1];
    float* out = (float*)d_out;

    cudaFuncSetAttribute(b_mma_kernel,   cudaFuncAttributeMaxDynamicSharedMemorySize, B2_SMEM);
    cudaFuncSetAttribute(lca_mma_kernel, cudaFuncAttributeMaxDynamicSharedMemorySize, LCA_SMEM);

    prep_kernel<<<288, 256>>>(dict);
    b_mma_kernel<<<NIMG * 7, 512, B2_SMEM>>>(image);
    lca_mma_kernel<<<NPB, 256, LCA_SMEM>>>();
    finalize_kernel<<<NIMG, NB>>>(out);
}